// round 3
// baseline (speedup 1.0000x reference)
#include <cuda_runtime.h>
#include <cstdint>

// TensorizedEmbedding: out[b, c] for token idx:
//   idx -> digits (d0,d1,d2,d3) over ROW_DIMS (8,10,20,20)
//   comboA = idx/400 = d0*10+d1   (80 values)
//   comboB = idx%400 = d2*20+d3   (400 values)
//   A[comboA][r2*16 + p], p = m0*4+m1   (16x16 per combo)  -- core0 x core1 over r1
//   B[comboB][r2*48 + q], q = m2*8+m3   (16x48 per combo)  -- core2 x core3 over r3
//   out[c] = sum_r2 A[p,r2]*B[r2,q],  c = p*48 + q

#define N_A (80 * 256)
#define N_B (400 * 768)

__device__ float g_A[N_A];   // [combo][r2*16 + p]
__device__ float g_B[N_B];   // [combo][r2*48 + q]

// ---------------------------------------------------------------------------
// Precompute A = core0 (x) core1 contracted over r1.
// core0: [1,8,4,16]   core0[0][d0][m0][r1]  at (d0*4+m0)*16 + r1
// core1: [16,10,4,16] core1[r1][d1][m1][r2] at ((r1*10+d1)*4+m1)*16 + r2
// ---------------------------------------------------------------------------
__global__ void build_A(const float* __restrict__ c0, const float* __restrict__ c1) {
    int t = blockIdx.x * blockDim.x + threadIdx.x;     // 20480 threads
    int combo = t >> 8;
    int w = t & 255;
    int r2 = w >> 4;
    int p  = w & 15;
    int m0 = p >> 2, m1 = p & 3;
    int d0 = combo / 10, d1 = combo - d0 * 10;
    const float* a = c0 + (d0 * 4 + m0) * 16;
    const float* b = c1 + (d1 * 4 + m1) * 16 + r2;     // stride 640 over r1
    float s = 0.f;
#pragma unroll
    for (int r1 = 0; r1 < 16; r1++)
        s += __ldg(a + r1) * __ldg(b + r1 * 640);
    g_A[t] = s;
}

// ---------------------------------------------------------------------------
// Precompute B = core2 (x) core3 contracted over r3.
// core2: [16,20,6,16] core2[r2][d2][m2][r3] at ((r2*20+d2)*6+m2)*16 + r3
// core3: [16,20,8,1]  core3[r3][d3][m3]     at (r3*20+d3)*8 + m3
// ---------------------------------------------------------------------------
__global__ void build_B(const float* __restrict__ c2, const float* __restrict__ c3) {
    int t = blockIdx.x * blockDim.x + threadIdx.x;     // 307200 threads
    int combo = t / 768;
    int w = t - combo * 768;
    int r2 = w / 48;
    int q  = w - r2 * 48;
    int m2 = q >> 3, m3 = q & 7;
    int d2 = combo / 20, d3 = combo - d2 * 20;
    const float* a = c2 + ((r2 * 20 + d2) * 6 + m2) * 16;
    const float* b = c3 + d3 * 8 + m3;                 // stride 160 over r3
    float s = 0.f;
#pragma unroll
    for (int r3 = 0; r3 < 16; r3++)
        s += __ldg(a + r3) * __ldg(b + r3 * 160);
    g_B[t] = s;
}

// ---------------------------------------------------------------------------
// Main kernel: 8 tokens per 128-thread block, 16 threads per token.
// Thread computes a 4(p) x 12(q) output tile via r2=16 dot.
// Padded smem strides (260 / 772 floats) avoid the stride==0 mod 32 bank
// conflict between the two tokens that share a warp.
// ---------------------------------------------------------------------------
#define TOK_PER_BLK 8
#define A_STRIDE 260    // 256 + 4 pad (float4-aligned)
#define B_STRIDE 772    // 768 + 4 pad

__global__ void __launch_bounds__(128)
tt_embed_kernel(const int* __restrict__ x, float* __restrict__ out, int ntok) {
    __shared__ float sA[TOK_PER_BLK * A_STRIDE];
    __shared__ float sB[TOK_PER_BLK * B_STRIDE];

    const int tok_l = threadIdx.x >> 4;       // 0..7
    const int lane  = threadIdx.x & 15;       // 0..15
    const int token = blockIdx.x * TOK_PER_BLK + tok_l;
    const bool live = (token < ntok);

    const int idx = live ? x[token] : 0;
    const int cA  = idx / 400;
    const int cB  = idx - cA * 400;

    // Stage this token's A (64 float4) and B (192 float4) into smem.
    const float4* gA4 = reinterpret_cast<const float4*>(g_A) + cA * 64;
    const float4* gB4 = reinterpret_cast<const float4*>(g_B) + cB * 192;
    float4* sA4 = reinterpret_cast<float4*>(sA + tok_l * A_STRIDE);
    float4* sB4 = reinterpret_cast<float4*>(sB + tok_l * B_STRIDE);
#pragma unroll
    for (int k = 0; k < 4; k++)  sA4[lane + 16 * k] = gA4[lane + 16 * k];
#pragma unroll
    for (int k = 0; k < 12; k++) sB4[lane + 16 * k] = gB4[lane + 16 * k];
    __syncthreads();

    const int pb = (lane >> 2) * 4;   // 0,4,8,12
    const int qb = (lane & 3) * 12;   // 0,12,24,36
    const float* As = sA + tok_l * A_STRIDE;
    const float* Bs = sB + tok_l * B_STRIDE;

    float acc[4][12];
#pragma unroll
    for (int i = 0; i < 4; i++)
#pragma unroll
        for (int j = 0; j < 12; j++) acc[i][j] = 0.f;

#pragma unroll
    for (int r = 0; r < 16; r++) {
        float4 a  = *reinterpret_cast<const float4*>(As + r * 16 + pb);
        float4 b0 = *reinterpret_cast<const float4*>(Bs + r * 48 + qb);
        float4 b1 = *reinterpret_cast<const float4*>(Bs + r * 48 + qb + 4);
        float4 b2 = *reinterpret_cast<const float4*>(Bs + r * 48 + qb + 8);
        float av[4]  = {a.x, a.y, a.z, a.w};
        float bv[12] = {b0.x, b0.y, b0.z, b0.w,
                        b1.x, b1.y, b1.z, b1.w,
                        b2.x, b2.y, b2.z, b2.w};
#pragma unroll
        for (int i = 0; i < 4; i++)
#pragma unroll
            for (int j = 0; j < 12; j++)
                acc[i][j] += av[i] * bv[j];
    }

    if (!live) return;
    float* o = out + (size_t)token * 768;
#pragma unroll
    for (int i = 0; i < 4; i++) {
#pragma unroll
        for (int jv = 0; jv < 3; jv++) {
            float4 v = make_float4(acc[i][jv * 4 + 0], acc[i][jv * 4 + 1],
                                   acc[i][jv * 4 + 2], acc[i][jv * 4 + 3]);
            *reinterpret_cast<float4*>(o + (pb + i) * 48 + qb + jv * 4) = v;
        }
    }
}

// ---------------------------------------------------------------------------
extern "C" void kernel_launch(void* const* d_in, const int* in_sizes, int n_in,
                              void* d_out, int out_size) {
    // Identify inputs by element count (all distinct):
    //   x: 32768 (int32), core0: 512, core1: 10240, core2: 30720, core3: 2560
    const int*   x  = nullptr;
    const float* c0 = nullptr; const float* c1 = nullptr;
    const float* c2 = nullptr; const float* c3 = nullptr;
    int ntok = 0;
    for (int i = 0; i < n_in; i++) {
        switch (in_sizes[i]) {
            case 512:   c0 = (const float*)d_in[i]; break;
            case 10240: c1 = (const float*)d_in[i]; break;
            case 30720: c2 = (const float*)d_in[i]; break;
            case 2560:  c3 = (const float*)d_in[i]; break;
            default:    x = (const int*)d_in[i]; ntok = in_sizes[i]; break;
        }
    }

    build_A<<<N_A / 256, 256>>>(c0, c1);
    build_B<<<N_B / 256, 256>>>(c2, c3);
    int nblk = (ntok + TOK_PER_BLK - 1) / TOK_PER_BLK;
    tt_embed_kernel<<<nblk, 128>>>(x, (float*)d_out, ntok);
}

// round 4
// speedup vs baseline: 1.0428x; 1.0428x over previous
#include <cuda_runtime.h>
#include <cstdint>

// TensorizedEmbedding: out[b, c] for token idx:
//   idx -> digits (d0,d1,d2,d3) over ROW_DIMS (8,10,20,20)
//   comboA = idx/400 = d0*10+d1   (80 values)
//   comboB = idx%400 = d2*20+d3   (400 values)
//   A[comboA][r2*16 + p], p = m0*4+m1   (16x16 per combo)  -- core0 x core1 over r1
//   B[comboB][r2*48 + q], q = m2*8+m3   (16x48 per combo)  -- core2 x core3 over r3
//   out[c] = sum_r2 A[p,r2]*B[r2,q],  c = p*48 + q

#define N_A (80 * 256)
#define N_B (400 * 768)

__device__ float g_A[N_A];   // [combo][r2*16 + p]
__device__ float g_B[N_B];   // [combo][r2*48 + q]

// ---- packed f32x2 helpers (Blackwell; ptxas will not auto-fuse these) ----
#define FMA2(acc, a2, b2) \
    asm("fma.rn.f32x2 %0, %1, %2, %0;" : "+l"(acc) : "l"(a2), "l"(b2))
#define PACK2(dst, lo, hi) \
    asm("mov.b64 %0, {%1, %2};" : "=l"(dst) : "r"(lo), "r"(hi))
#define UNPACK2(lo, hi, src) \
    asm("mov.b64 {%0, %1}, %2;" : "=r"(lo), "=r"(hi) : "l"(src))

// ---------------------------------------------------------------------------
// Fused precompute: blocks [0,80) build A, blocks [80,1280) build B.
// core0: [1,8,4,16]   core0[0][d0][m0][r1]  at (d0*4+m0)*16 + r1
// core1: [16,10,4,16] core1[r1][d1][m1][r2] at ((r1*10+d1)*4+m1)*16 + r2
// core2: [16,20,6,16] core2[r2][d2][m2][r3] at ((r2*20+d2)*6+m2)*16 + r3
// core3: [16,20,8,1]  core3[r3][d3][m3]     at (r3*20+d3)*8 + m3
// ---------------------------------------------------------------------------
__global__ void __launch_bounds__(256)
build_tables(const float* __restrict__ c0, const float* __restrict__ c1,
             const float* __restrict__ c2, const float* __restrict__ c3) {
    int blk = blockIdx.x;
    if (blk < 80) {
        int t = blk * 256 + threadIdx.x;               // 20480 threads -> A
        int combo = t >> 8;
        int w = t & 255;
        int r2 = w >> 4;
        int p  = w & 15;
        int m0 = p >> 2, m1 = p & 3;
        int d0 = combo / 10, d1 = combo - d0 * 10;
        const float* a = c0 + (d0 * 4 + m0) * 16;
        const float* b = c1 + (d1 * 4 + m1) * 16 + r2;  // stride 640 over r1
        float s = 0.f;
#pragma unroll
        for (int r1 = 0; r1 < 16; r1++)
            s += __ldg(a + r1) * __ldg(b + r1 * 640);
        g_A[t] = s;
    } else {
        int t = (blk - 80) * 256 + threadIdx.x;        // 307200 threads -> B
        int combo = t / 768;
        int w = t - combo * 768;
        int r2 = w / 48;
        int q  = w - r2 * 48;
        int m2 = q >> 3, m3 = q & 7;
        int d2 = combo / 20, d3 = combo - d2 * 20;
        const float* a = c2 + ((r2 * 20 + d2) * 6 + m2) * 16;
        const float* b = c3 + d3 * 8 + m3;             // stride 160 over r3
        float s = 0.f;
#pragma unroll
        for (int r3 = 0; r3 < 16; r3++)
            s += __ldg(a + r3) * __ldg(b + r3 * 160);
        g_B[t] = s;
    }
}

// ---------------------------------------------------------------------------
// Main kernel: 8 tokens per 128-thread block, 16 threads per token.
// Thread computes a 4(p) x 12(q) output tile via r2=16 dot, accumulating in
// packed f32x2 pairs (halves fma-pipe instruction count vs scalar FFMA).
// Padded smem strides (260 / 772 floats) avoid the stride==0 mod 32 bank
// conflict between the two tokens that share a warp.
// ---------------------------------------------------------------------------
#define TOK_PER_BLK 8
#define A_STRIDE 260    // 256 + 4 pad (float4-aligned)
#define B_STRIDE 772    // 768 + 4 pad

__global__ void __launch_bounds__(128)
tt_embed_kernel(const int* __restrict__ x, float* __restrict__ out, int ntok) {
    __shared__ float sA[TOK_PER_BLK * A_STRIDE];
    __shared__ float sB[TOK_PER_BLK * B_STRIDE];

    const int tok_l = threadIdx.x >> 4;       // 0..7
    const int lane  = threadIdx.x & 15;       // 0..15
    const int token = blockIdx.x * TOK_PER_BLK + tok_l;
    const bool live = (token < ntok);

    const int idx = live ? x[token] : 0;
    const int cA  = idx / 400;
    const int cB  = idx - cA * 400;

    // Stage this token's A (64 float4) and B (192 float4) into smem.
    const float4* gA4 = reinterpret_cast<const float4*>(g_A) + cA * 64;
    const float4* gB4 = reinterpret_cast<const float4*>(g_B) + cB * 192;
    float4* sA4 = reinterpret_cast<float4*>(sA + tok_l * A_STRIDE);
    float4* sB4 = reinterpret_cast<float4*>(sB + tok_l * B_STRIDE);
#pragma unroll
    for (int k = 0; k < 4; k++)  sA4[lane + 16 * k] = gA4[lane + 16 * k];
#pragma unroll
    for (int k = 0; k < 12; k++) sB4[lane + 16 * k] = gB4[lane + 16 * k];
    __syncthreads();

    const int pb = (lane >> 2) * 4;   // 0,4,8,12
    const int qb = (lane & 3) * 12;   // 0,12,24,36
    const float* As = sA + tok_l * A_STRIDE;
    const float* Bs = sB + tok_l * B_STRIDE;

    // acc[i][jp] = packed pair of outputs (q = qb+2*jp, qb+2*jp+1) for row pb+i
    unsigned long long acc[4][6];
#pragma unroll
    for (int i = 0; i < 4; i++)
#pragma unroll
        for (int j = 0; j < 6; j++) acc[i][j] = 0ull;

#pragma unroll
    for (int r = 0; r < 16; r++) {
        float4 a  = *reinterpret_cast<const float4*>(As + r * 16 + pb);
        float4 b0 = *reinterpret_cast<const float4*>(Bs + r * 48 + qb);
        float4 b1 = *reinterpret_cast<const float4*>(Bs + r * 48 + qb + 4);
        float4 b2 = *reinterpret_cast<const float4*>(Bs + r * 48 + qb + 8);

        // pack b into 6 f32x2 pairs
        unsigned long long bp[6];
        PACK2(bp[0], __float_as_uint(b0.x), __float_as_uint(b0.y));
        PACK2(bp[1], __float_as_uint(b0.z), __float_as_uint(b0.w));
        PACK2(bp[2], __float_as_uint(b1.x), __float_as_uint(b1.y));
        PACK2(bp[3], __float_as_uint(b1.z), __float_as_uint(b1.w));
        PACK2(bp[4], __float_as_uint(b2.x), __float_as_uint(b2.y));
        PACK2(bp[5], __float_as_uint(b2.z), __float_as_uint(b2.w));

        // broadcast-pack each a value
        unsigned long long ap[4];
        PACK2(ap[0], __float_as_uint(a.x), __float_as_uint(a.x));
        PACK2(ap[1], __float_as_uint(a.y), __float_as_uint(a.y));
        PACK2(ap[2], __float_as_uint(a.z), __float_as_uint(a.z));
        PACK2(ap[3], __float_as_uint(a.w), __float_as_uint(a.w));

#pragma unroll
        for (int i = 0; i < 4; i++)
#pragma unroll
            for (int j = 0; j < 6; j++)
                FMA2(acc[i][j], ap[i], bp[j]);
    }

    if (!live) return;
    float* o = out + (size_t)token * 768;
#pragma unroll
    for (int i = 0; i < 4; i++) {
#pragma unroll
        for (int jv = 0; jv < 3; jv++) {
            unsigned lo0, hi0, lo1, hi1;
            UNPACK2(lo0, hi0, acc[i][jv * 2 + 0]);
            UNPACK2(lo1, hi1, acc[i][jv * 2 + 1]);
            float4 v = make_float4(__uint_as_float(lo0), __uint_as_float(hi0),
                                   __uint_as_float(lo1), __uint_as_float(hi1));
            *reinterpret_cast<float4*>(o + (pb + i) * 48 + qb + jv * 4) = v;
        }
    }
}

// ---------------------------------------------------------------------------
extern "C" void kernel_launch(void* const* d_in, const int* in_sizes, int n_in,
                              void* d_out, int out_size) {
    // Identify inputs by element count (all distinct):
    //   x: 32768 (int32), core0: 512, core1: 10240, core2: 30720, core3: 2560
    const int*   x  = nullptr;
    const float* c0 = nullptr; const float* c1 = nullptr;
    const float* c2 = nullptr; const float* c3 = nullptr;
    int ntok = 0;
    for (int i = 0; i < n_in; i++) {
        switch (in_sizes[i]) {
            case 512:   c0 = (const float*)d_in[i]; break;
            case 10240: c1 = (const float*)d_in[i]; break;
            case 30720: c2 = (const float*)d_in[i]; break;
            case 2560:  c3 = (const float*)d_in[i]; break;
            default:    x = (const int*)d_in[i]; ntok = in_sizes[i]; break;
        }
    }

    build_tables<<<80 + N_B / 256, 256>>>(c0, c1, c2, c3);
    int nblk = (ntok + TOK_PER_BLK - 1) / TOK_PER_BLK;
    tt_embed_kernel<<<nblk, 128>>>(x, (float*)d_out, ntok);
}